// round 1
// baseline (speedup 1.0000x reference)
#include <cuda_runtime.h>
#include <cstdint>

#define DIM   768
#define HOUT  64
#define ROWS  128     // rows per CTA
#define NTH   128     // 4 warps
#define KC    64      // k-chunk for stage 1
#define SROW  68      // smem row stride in words (conflict-free + 16B aligned)

// Round-to-nearest tf32 conversion (truncation would bias dots by ~-1e-3).
__device__ __forceinline__ uint32_t f2tf(float f) {
    uint32_t u;
    asm("cvt.rna.tf32.f32 %0, %1;" : "=r"(u) : "f"(f));
    return u;
}

__device__ __forceinline__ void mma_tf32(float* c, const uint32_t* a, uint32_t b0, uint32_t b1) {
    asm volatile(
        "mma.sync.aligned.m16n8k8.row.col.f32.tf32.tf32.f32 "
        "{%0,%1,%2,%3}, {%4,%5,%6,%7}, {%8,%9}, {%0,%1,%2,%3};\n"
        : "+f"(c[0]), "+f"(c[1]), "+f"(c[2]), "+f"(c[3])
        : "r"(a[0]), "r"(a[1]), "r"(a[2]), "r"(a[3]), "r"(b0), "r"(b1));
}

// out = (x @ Wv^T + bv) @ Wo^T + bo
// (softmax over the singleton sequence axis in the reference is identically 1,
//  so q/k/scan are mathematically dead)
__global__ void __launch_bounds__(NTH)
fused_vo_kernel(const float* __restrict__ x,
                const float* __restrict__ Wv,
                const float* __restrict__ bv,
                const float* __restrict__ Wo,
                const float* __restrict__ bo,
                float* __restrict__ out,
                int nrows)
{
    extern __shared__ uint32_t smem[];
    uint32_t* xs = smem;               // [ROWS][SROW] : X chunk (tf32 bits), later V
    uint32_t* ws = smem + ROWS * SROW; // [64][SROW]   : weight chunk (tf32 bits)

    const int tid   = threadIdx.x;
    const int warp  = tid >> 5;
    const int lane  = tid & 31;
    const int g     = lane >> 2;   // groupID  (0..7)
    const int t     = lane & 3;    // threadID_in_group (0..3)
    const int row0  = blockIdx.x * ROWS;
    const int mbase = warp * 32;   // each warp owns 32 rows (2 m16 tiles)

    float acc[2][8][4];
#pragma unroll
    for (int mt = 0; mt < 2; mt++)
#pragma unroll
        for (int nt = 0; nt < 8; nt++)
#pragma unroll
            for (int i = 0; i < 4; i++) acc[mt][nt][i] = 0.f;

    // ================= stage 1: V = X @ Wv^T =================
    for (int k0 = 0; k0 < DIM; k0 += KC) {
        __syncthreads();  // previous chunk's smem readers done
        // X chunk: 128 x 64 floats = 2048 float4, 16 per thread, coalesced
#pragma unroll
        for (int p = 0; p < 16; p++) {
            int f  = p * NTH + tid;
            int r  = f >> 4;
            int c4 = (f & 15) << 2;
            float4 v = make_float4(0.f, 0.f, 0.f, 0.f);
            int gr = row0 + r;
            if (gr < nrows) v = *(const float4*)(x + (size_t)gr * DIM + k0 + c4);
            uint4 u;
            u.x = f2tf(v.x); u.y = f2tf(v.y); u.z = f2tf(v.z); u.w = f2tf(v.w);
            *(uint4*)(xs + r * SROW + c4) = u;
        }
        // Wv chunk: 64 x 64 floats = 1024 float4, 8 per thread
#pragma unroll
        for (int p = 0; p < 8; p++) {
            int f  = p * NTH + tid;
            int r  = f >> 4;
            int c4 = (f & 15) << 2;
            float4 v = *(const float4*)(Wv + (size_t)r * DIM + k0 + c4);
            uint4 u;
            u.x = f2tf(v.x); u.y = f2tf(v.y); u.z = f2tf(v.z); u.w = f2tf(v.w);
            *(uint4*)(ws + r * SROW + c4) = u;
        }
        __syncthreads();
#pragma unroll
        for (int ks = 0; ks < 8; ks++) {
            uint32_t a[2][4];
#pragma unroll
            for (int mt = 0; mt < 2; mt++) {
                int r = mbase + mt * 16 + g;
                a[mt][0] = xs[r * SROW + ks * 8 + t];
                a[mt][1] = xs[(r + 8) * SROW + ks * 8 + t];
                a[mt][2] = xs[r * SROW + ks * 8 + t + 4];
                a[mt][3] = xs[(r + 8) * SROW + ks * 8 + t + 4];
            }
#pragma unroll
            for (int nt = 0; nt < 8; nt++) {
                uint32_t b0 = ws[(nt * 8 + g) * SROW + ks * 8 + t];
                uint32_t b1 = ws[(nt * 8 + g) * SROW + ks * 8 + t + 4];
                mma_tf32(acc[0][nt], a[0], b0, b1);
                mma_tf32(acc[1][nt], a[1], b0, b1);
            }
        }
    }

    // write V (+bv), tf32-rounded, into xs. Rows are warp-private -> no race;
    // cross-warp visibility is established by the __syncthreads below.
#pragma unroll
    for (int mt = 0; mt < 2; mt++) {
#pragma unroll
        for (int nt = 0; nt < 8; nt++) {
            int col = nt * 8 + 2 * t;
            int r   = mbase + mt * 16 + g;
            float b0v = __ldg(bv + col);
            float b1v = __ldg(bv + col + 1);
            xs[r * SROW + col]           = f2tf(acc[mt][nt][0] + b0v);
            xs[r * SROW + col + 1]       = f2tf(acc[mt][nt][1] + b1v);
            xs[(r + 8) * SROW + col]     = f2tf(acc[mt][nt][2] + b0v);
            xs[(r + 8) * SROW + col + 1] = f2tf(acc[mt][nt][3] + b1v);
        }
    }

    // ================= stage 2: OUT = V @ Wo^T =================
    for (int n0 = 0; n0 < DIM; n0 += 64) {
        __syncthreads();  // protect ws overwrite (also publishes V on first iter)
        // Wo chunk: rows n0..n0+63, each 64 floats (contiguous) = 1024 float4
#pragma unroll
        for (int p = 0; p < 8; p++) {
            int f  = p * NTH + tid;
            int r  = f >> 4;
            int c4 = (f & 15) << 2;
            float4 v = *(const float4*)(Wo + (size_t)(n0 + r) * HOUT + c4);
            uint4 u;
            u.x = f2tf(v.x); u.y = f2tf(v.y); u.z = f2tf(v.z); u.w = f2tf(v.w);
            *(uint4*)(ws + r * SROW + c4) = u;
        }
        __syncthreads();
#pragma unroll
        for (int mt = 0; mt < 2; mt++)
#pragma unroll
            for (int nt = 0; nt < 8; nt++)
#pragma unroll
                for (int i = 0; i < 4; i++) acc[mt][nt][i] = 0.f;
#pragma unroll
        for (int ks = 0; ks < 8; ks++) {
            uint32_t a[2][4];
#pragma unroll
            for (int mt = 0; mt < 2; mt++) {
                int r = mbase + mt * 16 + g;
                a[mt][0] = xs[r * SROW + ks * 8 + t];
                a[mt][1] = xs[(r + 8) * SROW + ks * 8 + t];
                a[mt][2] = xs[r * SROW + ks * 8 + t + 4];
                a[mt][3] = xs[(r + 8) * SROW + ks * 8 + t + 4];
            }
#pragma unroll
            for (int nt = 0; nt < 8; nt++) {
                uint32_t b0 = ws[(nt * 8 + g) * SROW + ks * 8 + t];
                uint32_t b1 = ws[(nt * 8 + g) * SROW + ks * 8 + t + 4];
                mma_tf32(acc[0][nt], a[0], b0, b1);
                mma_tf32(acc[1][nt], a[1], b0, b1);
            }
        }
        // fused +bo, coalesced float2 stores (full 32B sectors per lane-quad)
#pragma unroll
        for (int mt = 0; mt < 2; mt++) {
#pragma unroll
            for (int nt = 0; nt < 8; nt++) {
                int col = n0 + nt * 8 + 2 * t;
                float bo0 = __ldg(bo + col);
                float bo1 = __ldg(bo + col + 1);
                int r = row0 + mbase + mt * 16 + g;
                if (r < nrows) {
                    float2 o = make_float2(acc[mt][nt][0] + bo0, acc[mt][nt][1] + bo1);
                    *(float2*)(out + (size_t)r * DIM + col) = o;
                }
                if (r + 8 < nrows) {
                    float2 o = make_float2(acc[mt][nt][2] + bo0, acc[mt][nt][3] + bo1);
                    *(float2*)(out + (size_t)(r + 8) * DIM + col) = o;
                }
            }
        }
    }
}

extern "C" void kernel_launch(void* const* d_in, const int* in_sizes, int n_in,
                              void* d_out, int out_size)
{
    // metadata order: x, q_state, Wq, bq, Wk, bk, Wv, bv, Wo, bo
    const float* x  = (const float*)d_in[0];
    const float* Wv = (const float*)d_in[6];
    const float* bv = (const float*)d_in[7];
    const float* Wo = (const float*)d_in[8];
    const float* bo = (const float*)d_in[9];
    float* out = (float*)d_out;

    int nrows = in_sizes[0] / DIM;
    int grid  = (nrows + ROWS - 1) / ROWS;
    int smem  = (ROWS * SROW + HOUT * SROW) * 4;  // 52224 B

    cudaFuncSetAttribute(fused_vo_kernel,
                         cudaFuncAttributeMaxDynamicSharedMemorySize, smem);
    fused_vo_kernel<<<grid, NTH, smem>>>(x, Wv, bv, Wo, bo, out, nrows);
}

// round 2
// speedup vs baseline: 1.3333x; 1.3333x over previous
#include <cuda_runtime.h>
#include <cstdint>

#define DIM   768
#define HOUT  64
#define ROWS  128
#define NTH   128
#define KC    32
#define NCH   24            // DIM/KC
#define XS    36            // x-chunk smem stride (words): banks (4g+t) all distinct
#define VS    68            // V / Wo-chunk stride (words), 64-wide rows

// smem word offsets (total 13824 words = 55296 B -> 4 CTAs/SM)
#define XBUF0 0
#define XBUF1 (128*XS)              // 4608
#define WBUF0 (2*128*XS)            // 9216
#define WBUF1 (2*128*XS + 64*XS)    // 11520
#define SMEM_BYTES ((2*128*XS + 2*64*XS)*4)
// stage2 reuse: V at word 0, stride 68 (128*68=8704 <= 9216)
//               Wo bufs at WBUF0 / WBUF0+32*VS (2*2176 <= 4608)

__device__ __align__(16) uint32_t g_wv[HOUT*DIM];   // tf32-rounded Wv bits
__device__ __align__(16) uint32_t g_wo[DIM*HOUT];   // tf32-rounded Wo bits

__device__ __forceinline__ uint32_t f2tf(float f) {
    uint32_t u;
    asm("cvt.rna.tf32.f32 %0, %1;" : "=r"(u) : "f"(f));
    return u;
}

__device__ __forceinline__ void mma_tf32(float* c, const uint32_t* a, uint32_t b0, uint32_t b1) {
    asm volatile(
        "mma.sync.aligned.m16n8k8.row.col.f32.tf32.tf32.f32 "
        "{%0,%1,%2,%3}, {%4,%5,%6,%7}, {%8,%9}, {%0,%1,%2,%3};\n"
        : "+f"(c[0]), "+f"(c[1]), "+f"(c[2]), "+f"(c[3])
        : "r"(a[0]), "r"(a[1]), "r"(a[2]), "r"(a[3]), "r"(b0), "r"(b1));
}

__device__ __forceinline__ void cpa16(uint32_t dst, const void* src) {
    asm volatile("cp.async.cg.shared.global [%0], [%1], 16;\n" :: "r"(dst), "l"(src));
}
#define CP_COMMIT() asm volatile("cp.async.commit_group;\n")
#define CP_WAIT1()  asm volatile("cp.async.wait_group 1;\n")
#define CP_WAIT0()  asm volatile("cp.async.wait_group 0;\n")

__global__ void prep_weights(const float* __restrict__ Wv, const float* __restrict__ Wo) {
    int i = blockIdx.x * blockDim.x + threadIdx.x;
    if (i < HOUT * DIM) {
        g_wv[i] = f2tf(Wv[i]);
        g_wo[i] = f2tf(Wo[i]);
    }
}

// out = (x @ Wv^T + bv) @ Wo^T + bo
// (softmax over the singleton sequence axis in the reference is identically 1,
//  so q/k/scan are mathematically dead)
__global__ void __launch_bounds__(NTH, 4)
fused_vo_kernel(const float* __restrict__ x,
                const float* __restrict__ bv,
                const float* __restrict__ bo,
                float* __restrict__ out,
                int nrows)
{
    extern __shared__ uint32_t sm[];
    uint32_t sbase;
    {
        uint64_t tmp;
        asm("cvta.to.shared.u64 %0, %1;" : "=l"(tmp) : "l"(sm));
        sbase = (uint32_t)tmp;
    }

    const int tid   = threadIdx.x;
    const int warp  = tid >> 5;
    const int lane  = tid & 31;
    const int g     = lane >> 2;
    const int t     = lane & 3;
    const int row0  = blockIdx.x * ROWS;
    const int mbase = warp * 32;        // 2 m16 tiles per warp

    // ---------------- per-thread staging coordinates ----------------
    // X chunk: 128 rows x 8 segs(16B); 1024 segs, 8/thread
    const int xr = tid >> 3;            // base row for p=0 (rows xr, xr+16, ...)
    const int xsg = tid & 7;            // 16B segment within row
    // Wv chunk: 64 rows x 8 segs; 512 segs, 4/thread
    // Wo chunk: 32 rows x 16 segs; 512 segs, 4/thread
    const int wor = tid >> 4;
    const int wos = tid & 15;

    float acc[2][8][4];
#pragma unroll
    for (int mt = 0; mt < 2; mt++)
#pragma unroll
        for (int nt = 0; nt < 8; nt++)
#pragma unroll
            for (int i = 0; i < 4; i++) acc[mt][nt][i] = 0.f;

    // ================= stage 1: V = X @ Wv^T =================
    // issue chunk c into buffer (c&1)
    auto stage1 = [&](int c) {
        const int xb = (c & 1) ? XBUF1 : XBUF0;
        const int wb = (c & 1) ? WBUF1 : WBUF0;
#pragma unroll
        for (int p = 0; p < 8; p++) {
            int r  = xr + p * 16;
            int gr = row0 + r; if (gr >= nrows) gr = nrows - 1;
            cpa16(sbase + (uint32_t)(xb + r * XS + xsg * 4) * 4,
                  x + (size_t)gr * DIM + c * KC + xsg * 4);
        }
#pragma unroll
        for (int p = 0; p < 4; p++) {
            int r = xr + p * 16;        // 0..63
            cpa16(sbase + (uint32_t)(wb + r * XS + xsg * 4) * 4,
                  g_wv + (size_t)r * DIM + c * KC + xsg * 4);
        }
        CP_COMMIT();
    };

    stage1(0);
#pragma unroll 1
    for (int c = 0; c < NCH; c++) {
        if (c < NCH - 1) { stage1(c + 1); CP_WAIT1(); }
        else             { CP_WAIT0(); }
        __syncthreads();
        const int xb = (c & 1) ? XBUF1 : XBUF0;
        const int wb = (c & 1) ? WBUF1 : WBUF0;
#pragma unroll
        for (int ks = 0; ks < 4; ks++) {
            uint32_t a[2][4];
#pragma unroll
            for (int mt = 0; mt < 2; mt++) {
                int r = mbase + mt * 16 + g;
                a[mt][0] = sm[xb + r * XS + ks * 8 + t];
                a[mt][1] = sm[xb + (r + 8) * XS + ks * 8 + t];
                a[mt][2] = sm[xb + r * XS + ks * 8 + t + 4];
                a[mt][3] = sm[xb + (r + 8) * XS + ks * 8 + t + 4];
            }
#pragma unroll
            for (int nt = 0; nt < 8; nt++) {
                uint32_t b0 = sm[wb + (nt * 8 + g) * XS + ks * 8 + t];
                uint32_t b1 = sm[wb + (nt * 8 + g) * XS + ks * 8 + t + 4];
                mma_tf32(acc[0][nt], a[0], b0, b1);
                mma_tf32(acc[1][nt], a[1], b0, b1);
            }
        }
        __syncthreads();   // safe to overwrite buf (c&1) next iteration
    }

    // write V (+bv), tf32-rounded, into word-0 region (stride VS).
    // rows are warp-private; published by stage-2's first barrier.
#pragma unroll
    for (int mt = 0; mt < 2; mt++) {
#pragma unroll
        for (int nt = 0; nt < 8; nt++) {
            int col = nt * 8 + 2 * t;
            int r   = mbase + mt * 16 + g;
            float b0v = __ldg(bv + col);
            float b1v = __ldg(bv + col + 1);
            sm[r * VS + col]           = f2tf(acc[mt][nt][0] + b0v);
            sm[r * VS + col + 1]       = f2tf(acc[mt][nt][1] + b1v);
            sm[(r + 8) * VS + col]     = f2tf(acc[mt][nt][2] + b0v);
            sm[(r + 8) * VS + col + 1] = f2tf(acc[mt][nt][3] + b1v);
        }
    }

    // ================= stage 2: OUT = V @ Wo^T =================
    // 24 n-chunks of 32 output columns, Wo chunks double-buffered in wbuf area
    auto stage2 = [&](int c) {
        const int wob = WBUF0 + (c & 1) * (32 * VS);
#pragma unroll
        for (int p = 0; p < 4; p++) {
            int r = wor + p * 8;        // 0..31
            cpa16(sbase + (uint32_t)(wob + r * VS + wos * 4) * 4,
                  g_wo + (size_t)(c * 32 + r) * HOUT + wos * 4);
        }
        CP_COMMIT();
    };

    stage2(0);
#pragma unroll 1
    for (int c = 0; c < NCH; c++) {
        if (c < NCH - 1) { stage2(c + 1); CP_WAIT1(); }
        else             { CP_WAIT0(); }
        __syncthreads();
        const int wob = WBUF0 + (c & 1) * (32 * VS);

        float acc2[2][4][4];
#pragma unroll
        for (int mt = 0; mt < 2; mt++)
#pragma unroll
            for (int nt = 0; nt < 4; nt++)
#pragma unroll
                for (int i = 0; i < 4; i++) acc2[mt][nt][i] = 0.f;

#pragma unroll
        for (int ks = 0; ks < 8; ks++) {
            uint32_t a[2][4];
#pragma unroll
            for (int mt = 0; mt < 2; mt++) {
                int r = mbase + mt * 16 + g;
                a[mt][0] = sm[r * VS + ks * 8 + t];
                a[mt][1] = sm[(r + 8) * VS + ks * 8 + t];
                a[mt][2] = sm[r * VS + ks * 8 + t + 4];
                a[mt][3] = sm[(r + 8) * VS + ks * 8 + t + 4];
            }
#pragma unroll
            for (int nt = 0; nt < 4; nt++) {
                uint32_t b0 = sm[wob + (nt * 8 + g) * VS + ks * 8 + t];
                uint32_t b1 = sm[wob + (nt * 8 + g) * VS + ks * 8 + t + 4];
                mma_tf32(acc2[0][nt], a[0], b0, b1);
                mma_tf32(acc2[1][nt], a[1], b0, b1);
            }
        }
        // fused +bo, coalesced float2 stores
        const int n0 = c * 32;
#pragma unroll
        for (int mt = 0; mt < 2; mt++) {
#pragma unroll
            for (int nt = 0; nt < 4; nt++) {
                int col = n0 + nt * 8 + 2 * t;
                float bo0 = __ldg(bo + col);
                float bo1 = __ldg(bo + col + 1);
                int r = row0 + mbase + mt * 16 + g;
                if (r < nrows) {
                    float2 o = make_float2(acc2[mt][nt][0] + bo0, acc2[mt][nt][1] + bo1);
                    *(float2*)(out + (size_t)r * DIM + col) = o;
                }
                if (r + 8 < nrows) {
                    float2 o = make_float2(acc2[mt][nt][2] + bo0, acc2[mt][nt][3] + bo1);
                    *(float2*)(out + (size_t)(r + 8) * DIM + col) = o;
                }
            }
        }
        __syncthreads();   // safe to overwrite Wo buf (c&1) next iteration
    }
}

extern "C" void kernel_launch(void* const* d_in, const int* in_sizes, int n_in,
                              void* d_out, int out_size)
{
    // metadata order: x, q_state, Wq, bq, Wk, bk, Wv, bv, Wo, bo
    const float* x  = (const float*)d_in[0];
    const float* Wv = (const float*)d_in[6];
    const float* bv = (const float*)d_in[7];
    const float* Wo = (const float*)d_in[8];
    const float* bo = (const float*)d_in[9];
    float* out = (float*)d_out;

    int nrows = in_sizes[0] / DIM;
    int grid  = (nrows + ROWS - 1) / ROWS;

    prep_weights<<<(HOUT * DIM + 255) / 256, 256>>>(Wv, Wo);

    cudaFuncSetAttribute(fused_vo_kernel,
                         cudaFuncAttributeMaxDynamicSharedMemorySize, SMEM_BYTES);
    fused_vo_kernel<<<grid, NTH, SMEM_BYTES>>>(x, bv, bo, out, nrows);
}